// round 10
// baseline (speedup 1.0000x reference)
#include <cuda_runtime.h>
#include <cuda_fp16.h>
#include <cstdint>

#define NN 100000
#define EE 1600000
#define INCH 128
#define HID 64
#define OUTC 40
#define ELLW 64   // max degree capacity; Poisson(16) -> P(deg>=64) ~ e^-40, safe

#define G1_BLOCKS ((NN + 127) / 128)   // 782
#define SC_BLOCKS 512

// ---------------- scratch (device globals; no allocation allowed) ----------------
__device__ int     g_cnt[NN];
__device__ int     g_adj[(size_t)NN * ELLW];   // ELL adjacency: sources of edges into node
__device__ float   g_dinv[NN];
// fp16 feature arrays are gathered with LDG.128 -> force 16B alignment.
__device__ __align__(16) __half g_xw[(size_t)NN * HID];   // dinv[r] * (x @ W1)[r]
__device__ float   g_h1[(size_t)NN * HID];                // relu(agg1), fp32 dense
__device__ __align__(16) __half g_h2[(size_t)NN * OUTC];  // dinv[r] * (h1 @ W2)[r]
__device__ int     g_is64;

// ---------------- packed f32x2 helpers (FFMA2: 2x fp32 FMA rate on sm_103a) ----------------
__device__ __forceinline__ unsigned long long pk2(float lo, float hi) {
    unsigned long long r;
    asm("mov.b64 %0, {%1, %2};" : "=l"(r) : "f"(lo), "f"(hi));
    return r;
}
__device__ __forceinline__ void upk2(unsigned long long v, float& lo, float& hi) {
    asm("mov.b64 {%0, %1}, %2;" : "=f"(lo), "=f"(hi) : "l"(v));
}
__device__ __forceinline__ void fma2(unsigned long long& d, unsigned long long a,
                                     unsigned long long b) {
    asm("fma.rn.f32x2 %0, %1, %2, %0;" : "+l"(d) : "l"(a), "l"(b));
}

// ---------------- init: zero counters + dtype sniff (fused) ----------------
__global__ void init_kernel(const void* ei) {
    int i = blockIdx.x * blockDim.x + threadIdx.x;
    if (i < NN) g_cnt[i] = 0;
    if (i == 0) {
        const unsigned int* w = (const unsigned int*)ei;
        int is64 = 1;
        for (int j = 0; j < 64; j++) {
            if (w[2 * j + 1] != 0u) { is64 = 0; break; }
        }
        g_is64 = is64;
    }
}

// ---------------- fused: GEMM1 (blocks [0,782)) + ELL scatter (blocks [782,1294)) ------------
// GEMM1: g_xw[N,64](fp16, UNSCALED) = x[N,128] @ W1[128,64]
//   256 threads, each 4 rows x 8 cols; W1 in smem (32KB); A via __ldg (L1-resident/block).
// Scatter: single-pass ELL build (count + place), independent of GEMM.
__global__ __launch_bounds__(256, 3) void fused_g1_scatter_kernel(
    const float* __restrict__ A, const float* __restrict__ W, const void* __restrict__ ei) {
    __shared__ float Ws[128 * 64];  // 32 KB

    int bx = blockIdx.x;
    if (bx >= G1_BLOCKS) {
        // ---- scatter path ----
        int tid = (bx - G1_BLOCKS) * 256 + threadIdx.x;
        int stride = SC_BLOCKS * 256;
        int is64 = g_is64;
        if (is64) {
            const longlong2* r2 = (const longlong2*)ei;
            const longlong2* c2 = (const longlong2*)((const long long*)ei + EE);
            for (int e = tid; e < EE / 2; e += stride) {
                longlong2 rr = __ldg(&r2[e]);
                longlong2 cc = __ldg(&c2[e]);
                int c0 = (int)cc.x, c1 = (int)cc.y;
                int p0 = atomicAdd(&g_cnt[c0], 1);
                int p1 = atomicAdd(&g_cnt[c1], 1);
                g_adj[(size_t)c0 * ELLW + p0] = (int)rr.x;
                g_adj[(size_t)c1 * ELLW + p1] = (int)rr.y;
            }
        } else {
            const int2* r2 = (const int2*)ei;
            const int2* c2 = (const int2*)((const int*)ei + EE);
            for (int e = tid; e < EE / 2; e += stride) {
                int2 rr = __ldg(&r2[e]);
                int2 cc = __ldg(&c2[e]);
                int p0 = atomicAdd(&g_cnt[cc.x], 1);
                int p1 = atomicAdd(&g_cnt[cc.y], 1);
                g_adj[(size_t)cc.x * ELLW + p0] = rr.x;
                g_adj[(size_t)cc.y * ELLW + p1] = rr.y;
            }
        }
        return;
    }

    // ---- GEMM path ----
    int tid = threadIdx.x;
    const float4* W4 = (const float4*)W;
    float4* Ws4 = (float4*)Ws;
#pragma unroll
    for (int i = 0; i < 8; i++) Ws4[tid + i * 256] = W4[tid + i * 256];  // 2048 float4
    __syncthreads();

    int m0 = bx * 128;
    int ty = tid >> 3, tx = tid & 7;   // ty 0..31, tx 0..7
    int r0 = m0 + ty * 4;
    int c0 = tx * 8;
    if (r0 + 4 > NN) return;           // NN % 4 == 0 -> whole quad valid or not

    unsigned long long acc2[4][4];
#pragma unroll
    for (int i = 0; i < 4; i++)
#pragma unroll
        for (int j = 0; j < 4; j++) acc2[i][j] = pk2(0.f, 0.f);

    const float4* A4 = (const float4*)A;  // 32 float4 per row
    for (int k4 = 0; k4 < 32; k4++) {
        float4 a[4];
#pragma unroll
        for (int i = 0; i < 4; i++) a[i] = __ldg(&A4[(size_t)(r0 + i) * 32 + k4]);
#pragma unroll
        for (int kk = 0; kk < 4; kk++) {
            const float* brow = &Ws[(k4 * 4 + kk) * 64 + c0];
            float4 b0 = *(const float4*)&brow[0];
            float4 b1 = *(const float4*)&brow[4];
            unsigned long long bp0 = pk2(b0.x, b0.y);
            unsigned long long bp1 = pk2(b0.z, b0.w);
            unsigned long long bp2 = pk2(b1.x, b1.y);
            unsigned long long bp3 = pk2(b1.z, b1.w);
#pragma unroll
            for (int i = 0; i < 4; i++) {
                float av = ((const float*)&a[i])[kk];
                unsigned long long av2 = pk2(av, av);
                fma2(acc2[i][0], av2, bp0);
                fma2(acc2[i][1], av2, bp1);
                fma2(acc2[i][2], av2, bp2);
                fma2(acc2[i][3], av2, bp3);
            }
        }
    }

#pragma unroll
    for (int i = 0; i < 4; i++) {
        __half2 h[4];
#pragma unroll
        for (int j = 0; j < 4; j++) {
            float lo, hi;
            upk2(acc2[i][j], lo, hi);
            h[j] = __floats2half2_rn(lo, hi);   // UNSCALED; dinv applied later
        }
        *(uint4*)&g_xw[(size_t)(r0 + i) * 64 + c0] = *(const uint4*)h;  // 16B aligned
    }
}

// ---------------- dinv + scale xw: di = rsqrt(cnt+1); g_xw *= di ----------------
__global__ void dinv_scale_kernel() {
    int gid = blockIdx.x * blockDim.x + threadIdx.x;
    int node = gid >> 3;
    int lane = gid & 7;
    if (node >= NN) return;
    float di = rsqrtf((float)(__ldg(&g_cnt[node]) + 1));  // +1 self-loop
    if (lane == 0) g_dinv[node] = di;
    uint4* p = (uint4*)&g_xw[(size_t)node * 64 + lane * 8];
    uint4 v = *p;
    __half2* hp = (__half2*)&v;
#pragma unroll
    for (int j = 0; j < 4; j++) {
        float2 f = __half22float2(hp[j]);
        hp[j] = __floats2half2_rn(di * f.x, di * f.y);
    }
    *p = v;
}

// ---------------- agg1: h1 = relu(dinv[c]*(sum_r scaled[r] + scaled[c]) + b1) ----------------
// 8 lanes per node; each lane handles 8 fp16 channels (16B LDG.128). 4-deep unrolled gathers.
__global__ void agg1_kernel(const float* __restrict__ b1) {
    int gid = blockIdx.x * blockDim.x + threadIdx.x;
    int node = gid >> 3;
    int lane = gid & 7;
    if (node >= NN) return;
    const uint4* xw = (const uint4*)g_xw;  // 64 halves = 8 uint4 per row

    float acc[8];
    {
        uint4 sv = __ldg(&xw[(size_t)node * 8 + lane]);  // = dinv[c]*h[c]  (self term)
        const __half2* hp = (const __half2*)&sv;
#pragma unroll
        for (int j = 0; j < 4; j++) {
            float2 f = __half22float2(hp[j]);
            acc[2 * j] = f.x;
            acc[2 * j + 1] = f.y;
        }
    }

    int s = node * ELLW;
    int e = s + __ldg(&g_cnt[node]);
    int k = s;
    for (; k + 4 <= e; k += 4) {
        int r0 = __ldg(&g_adj[k]);
        int r1 = __ldg(&g_adj[k + 1]);
        int r2 = __ldg(&g_adj[k + 2]);
        int r3 = __ldg(&g_adj[k + 3]);
        uint4 u0 = __ldg(&xw[(size_t)r0 * 8 + lane]);
        uint4 u1 = __ldg(&xw[(size_t)r1 * 8 + lane]);
        uint4 u2 = __ldg(&xw[(size_t)r2 * 8 + lane]);
        uint4 u3 = __ldg(&xw[(size_t)r3 * 8 + lane]);
        const __half2* p0 = (const __half2*)&u0;
        const __half2* p1 = (const __half2*)&u1;
        const __half2* p2 = (const __half2*)&u2;
        const __half2* p3 = (const __half2*)&u3;
#pragma unroll
        for (int j = 0; j < 4; j++) {
            float2 f0 = __half22float2(p0[j]);
            float2 f1 = __half22float2(p1[j]);
            float2 f2 = __half22float2(p2[j]);
            float2 f3 = __half22float2(p3[j]);
            acc[2 * j]     += (f0.x + f1.x) + (f2.x + f3.x);
            acc[2 * j + 1] += (f0.y + f1.y) + (f2.y + f3.y);
        }
    }
    for (; k < e; k++) {
        int r = __ldg(&g_adj[k]);
        uint4 u = __ldg(&xw[(size_t)r * 8 + lane]);
        const __half2* p = (const __half2*)&u;
#pragma unroll
        for (int j = 0; j < 4; j++) {
            float2 f = __half22float2(p[j]);
            acc[2 * j] += f.x;
            acc[2 * j + 1] += f.y;
        }
    }

    float di = __ldg(&g_dinv[node]);
    const float4* b14 = (const float4*)b1;
    float4 bb0 = __ldg(&b14[lane * 2]);
    float4 bb1 = __ldg(&b14[lane * 2 + 1]);
    float4 o0, o1;
    o0.x = fmaxf(fmaf(di, acc[0], bb0.x), 0.f);
    o0.y = fmaxf(fmaf(di, acc[1], bb0.y), 0.f);
    o0.z = fmaxf(fmaf(di, acc[2], bb0.z), 0.f);
    o0.w = fmaxf(fmaf(di, acc[3], bb0.w), 0.f);
    o1.x = fmaxf(fmaf(di, acc[4], bb1.x), 0.f);
    o1.y = fmaxf(fmaf(di, acc[5], bb1.y), 0.f);
    o1.z = fmaxf(fmaf(di, acc[6], bb1.z), 0.f);
    o1.w = fmaxf(fmaf(di, acc[7], bb1.w), 0.f);
    float4* dst = (float4*)&g_h1[(size_t)node * 64 + lane * 8];
    dst[0] = o0;
    dst[1] = o1;
}

// ---------------- GEMM2: g_h2[N,40](fp16) = dinv[row] * (h1[N,64] @ W2[64,40]) --------------
// 256 threads, each 4 rows x 5 cols; W2 in smem (10KB); h1 via __ldg.
__global__ __launch_bounds__(256, 3) void gemm2_kernel(const float* __restrict__ W) {
    __shared__ float Ws[64 * 40];  // 10240 B
    int tid = threadIdx.x;
    const float4* W4 = (const float4*)W;
    float4* Ws4 = (float4*)Ws;
#pragma unroll
    for (int i = 0; i < 3; i++) {
        int idx = tid + i * 256;
        if (idx < 640) Ws4[idx] = W4[idx];
    }
    __syncthreads();

    int m0 = blockIdx.x * 128;
    int ty = tid >> 3, tx = tid & 7;
    int r0 = m0 + ty * 4;
    int c0 = tx * 5;
    if (r0 + 4 > NN) return;

    unsigned long long acc2[4][2];
    float acc1[4];
#pragma unroll
    for (int i = 0; i < 4; i++) {
        acc2[i][0] = pk2(0.f, 0.f);
        acc2[i][1] = pk2(0.f, 0.f);
        acc1[i] = 0.f;
    }

    const float4* H4 = (const float4*)g_h1;  // 16 float4 per row
    for (int k4 = 0; k4 < 16; k4++) {
        float4 a[4];
#pragma unroll
        for (int i = 0; i < 4; i++) a[i] = __ldg(&H4[(size_t)(r0 + i) * 16 + k4]);
#pragma unroll
        for (int kk = 0; kk < 4; kk++) {
            const float* brow = &Ws[(k4 * 4 + kk) * 40 + c0];
            unsigned long long bp0 = pk2(brow[0], brow[1]);
            unsigned long long bp1 = pk2(brow[2], brow[3]);
            float b4 = brow[4];
#pragma unroll
            for (int i = 0; i < 4; i++) {
                float av = ((const float*)&a[i])[kk];
                unsigned long long av2 = pk2(av, av);
                fma2(acc2[i][0], av2, bp0);
                fma2(acc2[i][1], av2, bp1);
                acc1[i] = fmaf(av, b4, acc1[i]);
            }
        }
    }

    // Scalar __half stores: c0 = tx*5 is odd for odd tx (no half2 alignment).
#pragma unroll
    for (int i = 0; i < 4; i++) {
        int row = r0 + i;
        float di = __ldg(&g_dinv[row]);
        float v0, v1, v2, v3;
        upk2(acc2[i][0], v0, v1);
        upk2(acc2[i][1], v2, v3);
        __half* dst = &g_h2[(size_t)row * 40 + c0];
        dst[0] = __float2half_rn(di * v0);
        dst[1] = __float2half_rn(di * v1);
        dst[2] = __float2half_rn(di * v2);
        dst[3] = __float2half_rn(di * v3);
        dst[4] = __float2half_rn(di * acc1[i]);
    }
}

// ---------------- agg2: out = dinv[c]*(sum_r scaled[r] + scaled[c]) + b2 ----------------
// 5 lanes per node (6 nodes per warp, lanes 30,31 idle); each lane 8 fp16 ch (16B LDG.128).
__global__ void agg2_kernel(const float* __restrict__ b2, float* __restrict__ out) {
    int gtid = blockIdx.x * blockDim.x + threadIdx.x;
    int wid = gtid >> 5;
    int lane = gtid & 31;
    int g = lane / 5;
    int sub = lane - g * 5;
    if (g >= 6) return;
    int node = wid * 6 + g;
    if (node >= NN) return;
    const uint4* hh = (const uint4*)g_h2;  // 40 halves = 5 uint4 per row

    float acc[8];
    {
        uint4 sv = __ldg(&hh[(size_t)node * 5 + sub]);
        const __half2* hp = (const __half2*)&sv;
#pragma unroll
        for (int j = 0; j < 4; j++) {
            float2 f = __half22float2(hp[j]);
            acc[2 * j] = f.x;
            acc[2 * j + 1] = f.y;
        }
    }

    int s = node * ELLW;
    int e = s + __ldg(&g_cnt[node]);
    int k = s;
    for (; k + 4 <= e; k += 4) {
        int r0 = __ldg(&g_adj[k]);
        int r1 = __ldg(&g_adj[k + 1]);
        int r2 = __ldg(&g_adj[k + 2]);
        int r3 = __ldg(&g_adj[k + 3]);
        uint4 u0 = __ldg(&hh[(size_t)r0 * 5 + sub]);
        uint4 u1 = __ldg(&hh[(size_t)r1 * 5 + sub]);
        uint4 u2 = __ldg(&hh[(size_t)r2 * 5 + sub]);
        uint4 u3 = __ldg(&hh[(size_t)r3 * 5 + sub]);
        const __half2* p0 = (const __half2*)&u0;
        const __half2* p1 = (const __half2*)&u1;
        const __half2* p2 = (const __half2*)&u2;
        const __half2* p3 = (const __half2*)&u3;
#pragma unroll
        for (int j = 0; j < 4; j++) {
            float2 f0 = __half22float2(p0[j]);
            float2 f1 = __half22float2(p1[j]);
            float2 f2 = __half22float2(p2[j]);
            float2 f3 = __half22float2(p3[j]);
            acc[2 * j]     += (f0.x + f1.x) + (f2.x + f3.x);
            acc[2 * j + 1] += (f0.y + f1.y) + (f2.y + f3.y);
        }
    }
    for (; k < e; k++) {
        int r = __ldg(&g_adj[k]);
        uint4 u = __ldg(&hh[(size_t)r * 5 + sub]);
        const __half2* p = (const __half2*)&u;
#pragma unroll
        for (int j = 0; j < 4; j++) {
            float2 f = __half22float2(p[j]);
            acc[2 * j] += f.x;
            acc[2 * j + 1] += f.y;
        }
    }

    float di = __ldg(&g_dinv[node]);
    const float4* b24 = (const float4*)b2;
    float4 bb0 = __ldg(&b24[sub * 2]);
    float4 bb1 = __ldg(&b24[sub * 2 + 1]);
    float4 o0, o1;
    o0.x = fmaf(di, acc[0], bb0.x);
    o0.y = fmaf(di, acc[1], bb0.y);
    o0.z = fmaf(di, acc[2], bb0.z);
    o0.w = fmaf(di, acc[3], bb0.w);
    o1.x = fmaf(di, acc[4], bb1.x);
    o1.y = fmaf(di, acc[5], bb1.y);
    o1.z = fmaf(di, acc[6], bb1.z);
    o1.w = fmaf(di, acc[7], bb1.w);
    float4* dst = (float4*)&out[(size_t)node * 40 + sub * 8];
    dst[0] = o0;
    dst[1] = o1;
}

// ---------------- launch ----------------
extern "C" void kernel_launch(void* const* d_in, const int* in_sizes, int n_in,
                              void* d_out, int out_size) {
    const float* x  = (const float*)d_in[0];
    const void*  ei = d_in[1];
    const float* W1 = (const float*)d_in[2];
    const float* b1 = (const float*)d_in[3];
    const float* W2 = (const float*)d_in[4];
    const float* b2 = (const float*)d_in[5];
    float* out = (float*)d_out;

    init_kernel<<<(NN + 255) / 256, 256>>>(ei);
    fused_g1_scatter_kernel<<<G1_BLOCKS + SC_BLOCKS, 256>>>(x, W1, ei);
    dinv_scale_kernel<<<(NN * 8 + 255) / 256, 256>>>();
    agg1_kernel<<<(NN * 8 + 255) / 256, 256>>>(b1);
    gemm2_kernel<<<(NN + 127) / 128, 256>>>(W2);
    agg2_kernel<<<(NN + 47) / 48, 256>>>(b2, out);
}

// round 11
// speedup vs baseline: 1.0780x; 1.0780x over previous
#include <cuda_runtime.h>
#include <cuda_fp16.h>
#include <cstdint>

#define NN 100000
#define EE 1600000
#define INCH 128
#define HID 64
#define OUTC 40
#define ELLW 64   // max degree capacity; Poisson(16) -> P(deg>=64) ~ e^-40, safe

#define G1_BLOCKS ((NN + 127) / 128)   // 782
#define SC_BLOCKS 512

// ---------------- scratch (device globals; no allocation allowed) ----------------
__device__ int     g_cnt[NN];
__device__ __align__(16) int g_adj[(size_t)NN * ELLW];  // ELL adjacency (16B-aligned rows)
__device__ float   g_dinv[NN];
__device__ __align__(16) __half g_xw[(size_t)NN * HID];   // dinv[r] * (x @ W1)[r]
__device__ __align__(16) __half g_h1[(size_t)NN * HID];   // relu(agg1), fp16
__device__ __align__(16) __half g_h2[(size_t)NN * OUTC];  // dinv[r] * (h1 @ W2)[r]
__device__ int     g_is64;

// ---------------- packed f32x2 helpers (FFMA2: 2x fp32 FMA rate on sm_103a) ----------------
__device__ __forceinline__ unsigned long long pk2(float lo, float hi) {
    unsigned long long r;
    asm("mov.b64 %0, {%1, %2};" : "=l"(r) : "f"(lo), "f"(hi));
    return r;
}
__device__ __forceinline__ void upk2(unsigned long long v, float& lo, float& hi) {
    asm("mov.b64 {%0, %1}, %2;" : "=f"(lo), "=f"(hi) : "l"(v));
}
__device__ __forceinline__ void fma2(unsigned long long& d, unsigned long long a,
                                     unsigned long long b) {
    asm("fma.rn.f32x2 %0, %1, %2, %0;" : "+l"(d) : "l"(a), "l"(b));
}

// ---------------- init: zero counters + dtype sniff (fused) ----------------
__global__ void init_kernel(const void* ei) {
    int i = blockIdx.x * blockDim.x + threadIdx.x;
    if (i < NN) g_cnt[i] = 0;
    if (i == 0) {
        const unsigned int* w = (const unsigned int*)ei;
        int is64 = 1;
        for (int j = 0; j < 64; j++) {
            if (w[2 * j + 1] != 0u) { is64 = 0; break; }
        }
        g_is64 = is64;
    }
}

// ---------------- fused: GEMM1 (blocks [0,782)) + ELL scatter (blocks [782,1294)) ------------
__global__ __launch_bounds__(256, 3) void fused_g1_scatter_kernel(
    const float* __restrict__ A, const float* __restrict__ W, const void* __restrict__ ei) {
    __shared__ float Ws[128 * 64];  // 32 KB

    int bx = blockIdx.x;
    if (bx >= G1_BLOCKS) {
        // ---- scatter path ----
        int tid = (bx - G1_BLOCKS) * 256 + threadIdx.x;
        int stride = SC_BLOCKS * 256;
        int is64 = g_is64;
        if (is64) {
            const longlong2* r2 = (const longlong2*)ei;
            const longlong2* c2 = (const longlong2*)((const long long*)ei + EE);
            for (int e = tid; e < EE / 2; e += stride) {
                longlong2 rr = __ldg(&r2[e]);
                longlong2 cc = __ldg(&c2[e]);
                int c0 = (int)cc.x, c1 = (int)cc.y;
                int p0 = atomicAdd(&g_cnt[c0], 1);
                int p1 = atomicAdd(&g_cnt[c1], 1);
                g_adj[(unsigned)c0 * ELLW + p0] = (int)rr.x;
                g_adj[(unsigned)c1 * ELLW + p1] = (int)rr.y;
            }
        } else {
            const int2* r2 = (const int2*)ei;
            const int2* c2 = (const int2*)((const int*)ei + EE);
            for (int e = tid; e < EE / 2; e += stride) {
                int2 rr = __ldg(&r2[e]);
                int2 cc = __ldg(&c2[e]);
                int p0 = atomicAdd(&g_cnt[cc.x], 1);
                int p1 = atomicAdd(&g_cnt[cc.y], 1);
                g_adj[(unsigned)cc.x * ELLW + p0] = rr.x;
                g_adj[(unsigned)cc.y * ELLW + p1] = rr.y;
            }
        }
        return;
    }

    // ---- GEMM path: 256 threads, 4 rows x 8 cols each; W1 in smem; A via __ldg ----
    int tid = threadIdx.x;
    const float4* W4 = (const float4*)W;
    float4* Ws4 = (float4*)Ws;
#pragma unroll
    for (int i = 0; i < 8; i++) Ws4[tid + i * 256] = W4[tid + i * 256];
    __syncthreads();

    int m0 = bx * 128;
    int ty = tid >> 3, tx = tid & 7;
    int r0 = m0 + ty * 4;
    int c0 = tx * 8;
    if (r0 + 4 > NN) return;

    unsigned long long acc2[4][4];
#pragma unroll
    for (int i = 0; i < 4; i++)
#pragma unroll
        for (int j = 0; j < 4; j++) acc2[i][j] = pk2(0.f, 0.f);

    const float4* A4 = (const float4*)A;
    for (int k4 = 0; k4 < 32; k4++) {
        float4 a[4];
#pragma unroll
        for (int i = 0; i < 4; i++) a[i] = __ldg(&A4[(size_t)(r0 + i) * 32 + k4]);
#pragma unroll
        for (int kk = 0; kk < 4; kk++) {
            const float* brow = &Ws[(k4 * 4 + kk) * 64 + c0];
            float4 b0 = *(const float4*)&brow[0];
            float4 b1 = *(const float4*)&brow[4];
            unsigned long long bp0 = pk2(b0.x, b0.y);
            unsigned long long bp1 = pk2(b0.z, b0.w);
            unsigned long long bp2 = pk2(b1.x, b1.y);
            unsigned long long bp3 = pk2(b1.z, b1.w);
#pragma unroll
            for (int i = 0; i < 4; i++) {
                float av = ((const float*)&a[i])[kk];
                unsigned long long av2 = pk2(av, av);
                fma2(acc2[i][0], av2, bp0);
                fma2(acc2[i][1], av2, bp1);
                fma2(acc2[i][2], av2, bp2);
                fma2(acc2[i][3], av2, bp3);
            }
        }
    }

#pragma unroll
    for (int i = 0; i < 4; i++) {
        __half2 h[4];
#pragma unroll
        for (int j = 0; j < 4; j++) {
            float lo, hi;
            upk2(acc2[i][j], lo, hi);
            h[j] = __floats2half2_rn(lo, hi);   // UNSCALED; dinv applied later
        }
        *(uint4*)&g_xw[(unsigned)(r0 + i) * 64 + c0] = *(const uint4*)h;
    }
}

// ---------------- dinv + scale xw: di = rsqrt(cnt+1); g_xw *= di ----------------
__global__ void dinv_scale_kernel() {
    unsigned gid = blockIdx.x * blockDim.x + threadIdx.x;
    unsigned node = gid >> 3;
    unsigned lane = gid & 7;
    if (node >= NN) return;
    float di = rsqrtf((float)(__ldg(&g_cnt[node]) + 1));  // +1 self-loop
    if (lane == 0) g_dinv[node] = di;
    uint4* p = (uint4*)&g_xw[node * 64u + lane * 8u];
    uint4 v = *p;
    __half2* hp = (__half2*)&v;
#pragma unroll
    for (int j = 0; j < 4; j++) {
        float2 f = __half22float2(hp[j]);
        hp[j] = __floats2half2_rn(di * f.x, di * f.y);
    }
    *p = v;
}

// ---------------- agg helpers ----------------
// Accumulate two gathered uint4 (8 half2 lanes) into fp32 acc with one HADD2 level.
__device__ __forceinline__ void acc_pair(float* acc, const uint4& ua, const uint4& ub) {
    const __half2* pa = (const __half2*)&ua;
    const __half2* pb = (const __half2*)&ub;
#pragma unroll
    for (int j = 0; j < 4; j++) {
        float2 f = __half22float2(__hadd2(pa[j], pb[j]));
        acc[2 * j] += f.x;
        acc[2 * j + 1] += f.y;
    }
}
__device__ __forceinline__ void acc_one(float* acc, const uint4& u) {
    const __half2* p = (const __half2*)&u;
#pragma unroll
    for (int j = 0; j < 4; j++) {
        float2 f = __half22float2(p[j]);
        acc[2 * j] += f.x;
        acc[2 * j + 1] += f.y;
    }
}

// ---------------- agg1: h1 = relu(dinv[c]*(sum_r scaled[r] + scaled[c]) + b1) ----------------
// 8 lanes per node, 8 fp16 ch/lane; int4 index loads; 8-edge chunks (MLP=8); 32-bit addressing.
__global__ void agg1_kernel(const float* __restrict__ b1) {
    unsigned gid = blockIdx.x * blockDim.x + threadIdx.x;
    unsigned node = gid >> 3;
    unsigned lane = gid & 7;
    if (node >= NN) return;
    const uint4* xw = (const uint4*)g_xw;  // 8 uint4 per row

    float acc[8];
    {
        uint4 sv = __ldg(&xw[node * 8u + lane]);  // self term (prescaled)
        const __half2* hp = (const __half2*)&sv;
#pragma unroll
        for (int j = 0; j < 4; j++) {
            float2 f = __half22float2(hp[j]);
            acc[2 * j] = f.x;
            acc[2 * j + 1] = f.y;
        }
    }

    unsigned s = node * ELLW;
    unsigned e = s + (unsigned)__ldg(&g_cnt[node]);
    unsigned k = s;
    const int4* adj4 = (const int4*)g_adj;
    for (; k + 8 <= e; k += 8) {
        int4 i0 = __ldg(&adj4[k >> 2]);
        int4 i1 = __ldg(&adj4[(k >> 2) + 1]);
        uint4 u0 = __ldg(&xw[(unsigned)i0.x * 8u + lane]);
        uint4 u1 = __ldg(&xw[(unsigned)i0.y * 8u + lane]);
        uint4 u2 = __ldg(&xw[(unsigned)i0.z * 8u + lane]);
        uint4 u3 = __ldg(&xw[(unsigned)i0.w * 8u + lane]);
        uint4 u4 = __ldg(&xw[(unsigned)i1.x * 8u + lane]);
        uint4 u5 = __ldg(&xw[(unsigned)i1.y * 8u + lane]);
        uint4 u6 = __ldg(&xw[(unsigned)i1.z * 8u + lane]);
        uint4 u7 = __ldg(&xw[(unsigned)i1.w * 8u + lane]);
        acc_pair(acc, u0, u1);
        acc_pair(acc, u2, u3);
        acc_pair(acc, u4, u5);
        acc_pair(acc, u6, u7);
    }
    for (; k + 2 <= e; k += 2) {
        int r0 = __ldg(&g_adj[k]);
        int r1 = __ldg(&g_adj[k + 1]);
        uint4 u0 = __ldg(&xw[(unsigned)r0 * 8u + lane]);
        uint4 u1 = __ldg(&xw[(unsigned)r1 * 8u + lane]);
        acc_pair(acc, u0, u1);
    }
    if (k < e) {
        int r = __ldg(&g_adj[k]);
        uint4 u = __ldg(&xw[(unsigned)r * 8u + lane]);
        acc_one(acc, u);
    }

    float di = __ldg(&g_dinv[node]);
    const float4* b14 = (const float4*)b1;
    float4 bb0 = __ldg(&b14[lane * 2]);
    float4 bb1 = __ldg(&b14[lane * 2 + 1]);
    __half2 o[4];
    o[0] = __floats2half2_rn(fmaxf(fmaf(di, acc[0], bb0.x), 0.f),
                             fmaxf(fmaf(di, acc[1], bb0.y), 0.f));
    o[1] = __floats2half2_rn(fmaxf(fmaf(di, acc[2], bb0.z), 0.f),
                             fmaxf(fmaf(di, acc[3], bb0.w), 0.f));
    o[2] = __floats2half2_rn(fmaxf(fmaf(di, acc[4], bb1.x), 0.f),
                             fmaxf(fmaf(di, acc[5], bb1.y), 0.f));
    o[3] = __floats2half2_rn(fmaxf(fmaf(di, acc[6], bb1.z), 0.f),
                             fmaxf(fmaf(di, acc[7], bb1.w), 0.f));
    *(uint4*)&g_h1[node * 64u + lane * 8u] = *(const uint4*)o;
}

// ---------------- GEMM2: g_h2[N,40](fp16) = dinv[row] * (h1(fp16)[N,64] @ W2[64,40]) --------
// 256 threads, each 4 rows x 5 cols; W2 in smem; h1 via __ldg (uint4 of 8 halves).
__global__ __launch_bounds__(256, 3) void gemm2_kernel(const float* __restrict__ W) {
    __shared__ float Ws[64 * 40];  // 10240 B
    int tid = threadIdx.x;
    const float4* W4 = (const float4*)W;
    float4* Ws4 = (float4*)Ws;
#pragma unroll
    for (int i = 0; i < 3; i++) {
        int idx = tid + i * 256;
        if (idx < 640) Ws4[idx] = W4[idx];
    }
    __syncthreads();

    int m0 = blockIdx.x * 128;
    int ty = tid >> 3, tx = tid & 7;
    int r0 = m0 + ty * 4;
    int c0 = tx * 5;
    if (r0 + 4 > NN) return;

    unsigned long long acc2[4][2];
    float acc1[4];
#pragma unroll
    for (int i = 0; i < 4; i++) {
        acc2[i][0] = pk2(0.f, 0.f);
        acc2[i][1] = pk2(0.f, 0.f);
        acc1[i] = 0.f;
    }

    const uint4* H8 = (const uint4*)g_h1;  // 8 uint4 (of 8 halves) per row
    for (int k8 = 0; k8 < 8; k8++) {
        float a[4][8];
#pragma unroll
        for (int i = 0; i < 4; i++) {
            uint4 v = __ldg(&H8[(unsigned)(r0 + i) * 8u + k8]);
            const __half2* hp = (const __half2*)&v;
#pragma unroll
            for (int j = 0; j < 4; j++) {
                float2 f = __half22float2(hp[j]);
                a[i][2 * j] = f.x;
                a[i][2 * j + 1] = f.y;
            }
        }
#pragma unroll
        for (int kk = 0; kk < 8; kk++) {
            const float* brow = &Ws[(k8 * 8 + kk) * 40 + c0];
            unsigned long long bp0 = pk2(brow[0], brow[1]);
            unsigned long long bp1 = pk2(brow[2], brow[3]);
            float b4 = brow[4];
#pragma unroll
            for (int i = 0; i < 4; i++) {
                float av = a[i][kk];
                unsigned long long av2 = pk2(av, av);
                fma2(acc2[i][0], av2, bp0);
                fma2(acc2[i][1], av2, bp1);
                acc1[i] = fmaf(av, b4, acc1[i]);
            }
        }
    }

    // Scalar __half stores: c0 = tx*5 is odd for odd tx (no half2 alignment).
#pragma unroll
    for (int i = 0; i < 4; i++) {
        int row = r0 + i;
        float di = __ldg(&g_dinv[row]);
        float v0, v1, v2, v3;
        upk2(acc2[i][0], v0, v1);
        upk2(acc2[i][1], v2, v3);
        __half* dst = &g_h2[(unsigned)row * 40 + c0];
        dst[0] = __float2half_rn(di * v0);
        dst[1] = __float2half_rn(di * v1);
        dst[2] = __float2half_rn(di * v2);
        dst[3] = __float2half_rn(di * v3);
        dst[4] = __float2half_rn(di * acc1[i]);
    }
}

// ---------------- agg2: out = dinv[c]*(sum_r scaled[r] + scaled[c]) + b2 ----------------
// 5 lanes per node (6 nodes/warp); int4 index loads; 8-edge chunks; 32-bit addressing.
__global__ void agg2_kernel(const float* __restrict__ b2, float* __restrict__ out) {
    unsigned gtid = blockIdx.x * blockDim.x + threadIdx.x;
    unsigned wid = gtid >> 5;
    unsigned lane = gtid & 31;
    unsigned g = lane / 5;
    unsigned sub = lane - g * 5;
    if (g >= 6) return;
    unsigned node = wid * 6 + g;
    if (node >= NN) return;
    const uint4* hh = (const uint4*)g_h2;  // 5 uint4 per row

    float acc[8];
    {
        uint4 sv = __ldg(&hh[node * 5u + sub]);
        const __half2* hp = (const __half2*)&sv;
#pragma unroll
        for (int j = 0; j < 4; j++) {
            float2 f = __half22float2(hp[j]);
            acc[2 * j] = f.x;
            acc[2 * j + 1] = f.y;
        }
    }

    unsigned s = node * ELLW;
    unsigned e = s + (unsigned)__ldg(&g_cnt[node]);
    unsigned k = s;
    const int4* adj4 = (const int4*)g_adj;
    for (; k + 8 <= e; k += 8) {
        int4 i0 = __ldg(&adj4[k >> 2]);
        int4 i1 = __ldg(&adj4[(k >> 2) + 1]);
        uint4 u0 = __ldg(&hh[(unsigned)i0.x * 5u + sub]);
        uint4 u1 = __ldg(&hh[(unsigned)i0.y * 5u + sub]);
        uint4 u2 = __ldg(&hh[(unsigned)i0.z * 5u + sub]);
        uint4 u3 = __ldg(&hh[(unsigned)i0.w * 5u + sub]);
        uint4 u4 = __ldg(&hh[(unsigned)i1.x * 5u + sub]);
        uint4 u5 = __ldg(&hh[(unsigned)i1.y * 5u + sub]);
        uint4 u6 = __ldg(&hh[(unsigned)i1.z * 5u + sub]);
        uint4 u7 = __ldg(&hh[(unsigned)i1.w * 5u + sub]);
        acc_pair(acc, u0, u1);
        acc_pair(acc, u2, u3);
        acc_pair(acc, u4, u5);
        acc_pair(acc, u6, u7);
    }
    for (; k + 2 <= e; k += 2) {
        int r0 = __ldg(&g_adj[k]);
        int r1 = __ldg(&g_adj[k + 1]);
        uint4 u0 = __ldg(&hh[(unsigned)r0 * 5u + sub]);
        uint4 u1 = __ldg(&hh[(unsigned)r1 * 5u + sub]);
        acc_pair(acc, u0, u1);
    }
    if (k < e) {
        int r = __ldg(&g_adj[k]);
        uint4 u = __ldg(&hh[(unsigned)r * 5u + sub]);
        acc_one(acc, u);
    }

    float di = __ldg(&g_dinv[node]);
    const float4* b24 = (const float4*)b2;
    float4 bb0 = __ldg(&b24[sub * 2]);
    float4 bb1 = __ldg(&b24[sub * 2 + 1]);
    float4 o0, o1;
    o0.x = fmaf(di, acc[0], bb0.x);
    o0.y = fmaf(di, acc[1], bb0.y);
    o0.z = fmaf(di, acc[2], bb0.z);
    o0.w = fmaf(di, acc[3], bb0.w);
    o1.x = fmaf(di, acc[4], bb1.x);
    o1.y = fmaf(di, acc[5], bb1.y);
    o1.z = fmaf(di, acc[6], bb1.z);
    o1.w = fmaf(di, acc[7], bb1.w);
    float4* dst = (float4*)&out[(unsigned)node * 40 + sub * 8];
    dst[0] = o0;
    dst[1] = o1;
}

// ---------------- launch ----------------
extern "C" void kernel_launch(void* const* d_in, const int* in_sizes, int n_in,
                              void* d_out, int out_size) {
    const float* x  = (const float*)d_in[0];
    const void*  ei = d_in[1];
    const float* W1 = (const float*)d_in[2];
    const float* b1 = (const float*)d_in[3];
    const float* W2 = (const float*)d_in[4];
    const float* b2 = (const float*)d_in[5];
    float* out = (float*)d_out;

    init_kernel<<<(NN + 255) / 256, 256>>>(ei);
    fused_g1_scatter_kernel<<<G1_BLOCKS + SC_BLOCKS, 256>>>(x, W1, ei);
    dinv_scale_kernel<<<(NN * 8 + 255) / 256, 256>>>();
    agg1_kernel<<<(NN * 8 + 255) / 256, 256>>>(b1);
    gemm2_kernel<<<(NN + 127) / 128, 256>>>(W2);
    agg2_kernel<<<(NN + 47) / 48, 256>>>(b2, out);
}

// round 12
// speedup vs baseline: 1.3255x; 1.2296x over previous
#include <cuda_runtime.h>
#include <cuda_fp16.h>
#include <cstdint>

#define NN 100000
#define EE 1600000
#define INCH 128
#define HID 64
#define OUTC 40
#define ELLW 64   // max degree capacity; Poisson(16) -> P(deg>=64) ~ e^-40, safe

#define G1_BLOCKS ((NN + 127) / 128)   // 782
#define SC_BLOCKS 512
#define SP 136    // smem stride (halves) for W^T tiles: conflict-free for the B-fragment LDS

// ---------------- scratch (device globals; no allocation allowed) ----------------
__device__ int     g_cnt[NN];
__device__ __align__(16) int g_adj[(size_t)NN * ELLW];  // ELL adjacency (16B-aligned rows)
__device__ float   g_dinv[NN];
__device__ __align__(16) __half g_xw[(size_t)NN * HID];   // dinv[r] * (x @ W1)[r]
__device__ __align__(16) __half g_h1[(size_t)NN * HID];   // relu(agg1), fp16
__device__ __align__(16) __half g_h2[(size_t)NN * OUTC];  // dinv[r] * (h1 @ W2)[r]
__device__ int     g_is64;

// ---------------- packed f32x2 helpers (FFMA2: 2x fp32 FMA rate on sm_103a) ----------------
__device__ __forceinline__ unsigned long long pk2(float lo, float hi) {
    unsigned long long r;
    asm("mov.b64 %0, {%1, %2};" : "=l"(r) : "f"(lo), "f"(hi));
    return r;
}
__device__ __forceinline__ void upk2(unsigned long long v, float& lo, float& hi) {
    asm("mov.b64 {%0, %1}, %2;" : "=f"(lo), "=f"(hi) : "l"(v));
}
__device__ __forceinline__ void fma2(unsigned long long& d, unsigned long long a,
                                     unsigned long long b) {
    asm("fma.rn.f32x2 %0, %1, %2, %0;" : "+l"(d) : "l"(a), "l"(b));
}

// ---------------- HMMA m16n8k16 (row.col, f16 in, f32 acc) ----------------
__device__ __forceinline__ void mma16816(float* d, const unsigned* a, unsigned b0, unsigned b1) {
    asm volatile(
        "mma.sync.aligned.m16n8k16.row.col.f32.f16.f16.f32 "
        "{%0,%1,%2,%3}, {%4,%5,%6,%7}, {%8,%9}, {%0,%1,%2,%3};"
        : "+f"(d[0]), "+f"(d[1]), "+f"(d[2]), "+f"(d[3])
        : "r"(a[0]), "r"(a[1]), "r"(a[2]), "r"(a[3]), "r"(b0), "r"(b1));
}

// split float2 -> hi half2 + lo (residual) half2
__device__ __forceinline__ void split_f2(float2 f, unsigned& hi, unsigned& lo) {
    __half2 h = __floats2half2_rn(f.x, f.y);
    float2 hf = __half22float2(h);
    __half2 l = __floats2half2_rn(f.x - hf.x, f.y - hf.y);
    hi = *(unsigned*)&h;
    lo = *(unsigned*)&l;
}

// ---------------- init: zero counters + dtype sniff (fused) ----------------
__global__ void init_kernel(const void* ei) {
    int i = blockIdx.x * blockDim.x + threadIdx.x;
    if (i < NN) g_cnt[i] = 0;
    if (i == 0) {
        const unsigned int* w = (const unsigned int*)ei;
        int is64 = 1;
        for (int j = 0; j < 64; j++) {
            if (w[2 * j + 1] != 0u) { is64 = 0; break; }
        }
        g_is64 = is64;
    }
}

// ---------------- fused: tensor-core GEMM1 (blocks [0,782)) + ELL scatter ----------------
// GEMM1: g_xw[N,64](fp16, UNSCALED) = x[N,128] @ W1[128,64]
//   8 warps x (16 rows x 64 cols) per block. A fragments from gmem (fp32 -> hi/lo fp16 split),
//   W1^T hi/lo in smem. 3 HMMAs per site (Ah*Bh + Ah*Bl + Al*Bh) -> fp32-level accuracy.
__global__ __launch_bounds__(256) void fused_g1_scatter_kernel(
    const float* __restrict__ A, const float* __restrict__ W, const void* __restrict__ ei) {
    __shared__ __half Wh[64 * SP];
    __shared__ __half Wl[64 * SP];

    int bx = blockIdx.x;
    if (bx >= G1_BLOCKS) {
        // ---- scatter path ----
        int tid = (bx - G1_BLOCKS) * 256 + threadIdx.x;
        int stride = SC_BLOCKS * 256;
        int is64 = g_is64;
        if (is64) {
            const longlong2* r2 = (const longlong2*)ei;
            const longlong2* c2 = (const longlong2*)((const long long*)ei + EE);
            for (int e = tid; e < EE / 2; e += stride) {
                longlong2 rr = __ldg(&r2[e]);
                longlong2 cc = __ldg(&c2[e]);
                int c0 = (int)cc.x, c1 = (int)cc.y;
                int p0 = atomicAdd(&g_cnt[c0], 1);
                int p1 = atomicAdd(&g_cnt[c1], 1);
                g_adj[(unsigned)c0 * ELLW + p0] = (int)rr.x;
                g_adj[(unsigned)c1 * ELLW + p1] = (int)rr.y;
            }
        } else {
            const int2* r2 = (const int2*)ei;
            const int2* c2 = (const int2*)((const int*)ei + EE);
            for (int e = tid; e < EE / 2; e += stride) {
                int2 rr = __ldg(&r2[e]);
                int2 cc = __ldg(&c2[e]);
                int p0 = atomicAdd(&g_cnt[cc.x], 1);
                int p1 = atomicAdd(&g_cnt[cc.y], 1);
                g_adj[(unsigned)cc.x * ELLW + p0] = rr.x;
                g_adj[(unsigned)cc.y * ELLW + p1] = rr.y;
            }
        }
        return;
    }

    // ---- GEMM path ----
    int tid = threadIdx.x;
    // Build W^T hi/lo in smem: Wh[n*SP + k] = hi(W[k][n]), Wl = residual.
    for (int idx = tid; idx < 128 * 64; idx += 256) {
        int k = idx >> 6, n = idx & 63;
        float w = __ldg(&W[idx]);
        __half h = __float2half_rn(w);
        Wh[n * SP + k] = h;
        Wl[n * SP + k] = __float2half_rn(w - __half2float(h));
    }
    __syncthreads();

    int warp = tid >> 5, lane = tid & 31;
    int g = lane >> 2, t = lane & 3;
    int row0 = bx * 128 + warp * 16 + g;    // rows row0 and row0+8
    int ra = (row0 < NN) ? row0 : (NN - 1);
    int rb = (row0 + 8 < NN) ? (row0 + 8) : (NN - 1);
    const float* Ar0 = A + (size_t)ra * 128;
    const float* Ar1 = A + (size_t)rb * 128;

    float d[8][4];
#pragma unroll
    for (int j = 0; j < 8; j++)
#pragma unroll
        for (int q = 0; q < 4; q++) d[j][q] = 0.f;

#pragma unroll
    for (int kk = 0; kk < 8; kk++) {
        int kb = kk * 16 + t * 2;
        float2 L0 = __ldg((const float2*)(Ar0 + kb));       // a0: (g,   kb..kb+1)
        float2 L1 = __ldg((const float2*)(Ar1 + kb));       // a1: (g+8, kb..kb+1)
        float2 L2 = __ldg((const float2*)(Ar0 + kb + 8));   // a2: (g,   kb+8..9)
        float2 L3 = __ldg((const float2*)(Ar1 + kb + 8));   // a3: (g+8, kb+8..9)
        unsigned ah[4], al[4];
        split_f2(L0, ah[0], al[0]);
        split_f2(L1, ah[1], al[1]);
        split_f2(L2, ah[2], al[2]);
        split_f2(L3, ah[3], al[3]);
#pragma unroll
        for (int j = 0; j < 8; j++) {
            int n = j * 8 + g;
            const __half* ph = &Wh[n * SP + kk * 16 + t * 2];
            const __half* pl = &Wl[n * SP + kk * 16 + t * 2];
            unsigned bh0 = *(const unsigned*)ph;
            unsigned bh1 = *(const unsigned*)(ph + 8);
            unsigned bl0 = *(const unsigned*)pl;
            unsigned bl1 = *(const unsigned*)(pl + 8);
            mma16816(d[j], ah, bh0, bh1);
            mma16816(d[j], ah, bl0, bl1);
            mma16816(d[j], al, bh0, bh1);
        }
    }

    // Epilogue: d[j] = {(g,c0),(g,c0+1),(g+8,c0),(g+8,c0+1)}, c0 = j*8 + t*2. UNSCALED fp16.
#pragma unroll
    for (int j = 0; j < 8; j++) {
        int c0 = j * 8 + t * 2;
        if (row0 < NN) {
            __half2 p = __floats2half2_rn(d[j][0], d[j][1]);
            *(unsigned*)&g_xw[(unsigned)row0 * 64 + c0] = *(unsigned*)&p;
        }
        if (row0 + 8 < NN) {
            __half2 p = __floats2half2_rn(d[j][2], d[j][3]);
            *(unsigned*)&g_xw[(unsigned)(row0 + 8) * 64 + c0] = *(unsigned*)&p;
        }
    }
}

// ---------------- dinv + scale xw: di = rsqrt(cnt+1); g_xw *= di ----------------
__global__ void dinv_scale_kernel() {
    unsigned gid = blockIdx.x * blockDim.x + threadIdx.x;
    unsigned node = gid >> 3;
    unsigned lane = gid & 7;
    if (node >= NN) return;
    float di = rsqrtf((float)(__ldg(&g_cnt[node]) + 1));  // +1 self-loop
    if (lane == 0) g_dinv[node] = di;
    uint4* p = (uint4*)&g_xw[node * 64u + lane * 8u];
    uint4 v = *p;
    __half2* hp = (__half2*)&v;
#pragma unroll
    for (int j = 0; j < 4; j++) {
        float2 f = __half22float2(hp[j]);
        hp[j] = __floats2half2_rn(di * f.x, di * f.y);
    }
    *p = v;
}

// ---------------- agg helpers ----------------
__device__ __forceinline__ void acc_pair(float* acc, const uint4& ua, const uint4& ub) {
    const __half2* pa = (const __half2*)&ua;
    const __half2* pb = (const __half2*)&ub;
#pragma unroll
    for (int j = 0; j < 4; j++) {
        float2 f = __half22float2(__hadd2(pa[j], pb[j]));
        acc[2 * j] += f.x;
        acc[2 * j + 1] += f.y;
    }
}
__device__ __forceinline__ void acc_one(float* acc, const uint4& u) {
    const __half2* p = (const __half2*)&u;
#pragma unroll
    for (int j = 0; j < 4; j++) {
        float2 f = __half22float2(p[j]);
        acc[2 * j] += f.x;
        acc[2 * j + 1] += f.y;
    }
}

// ---------------- agg1: h1 = relu(dinv[c]*(sum_r scaled[r] + scaled[c]) + b1) ----------------
__global__ void agg1_kernel(const float* __restrict__ b1) {
    unsigned gid = blockIdx.x * blockDim.x + threadIdx.x;
    unsigned node = gid >> 3;
    unsigned lane = gid & 7;
    if (node >= NN) return;
    const uint4* xw = (const uint4*)g_xw;

    float acc[8];
    {
        uint4 sv = __ldg(&xw[node * 8u + lane]);
        const __half2* hp = (const __half2*)&sv;
#pragma unroll
        for (int j = 0; j < 4; j++) {
            float2 f = __half22float2(hp[j]);
            acc[2 * j] = f.x;
            acc[2 * j + 1] = f.y;
        }
    }

    unsigned s = node * ELLW;
    unsigned e = s + (unsigned)__ldg(&g_cnt[node]);
    unsigned k = s;
    const int4* adj4 = (const int4*)g_adj;
    for (; k + 8 <= e; k += 8) {
        int4 i0 = __ldg(&adj4[k >> 2]);
        int4 i1 = __ldg(&adj4[(k >> 2) + 1]);
        uint4 u0 = __ldg(&xw[(unsigned)i0.x * 8u + lane]);
        uint4 u1 = __ldg(&xw[(unsigned)i0.y * 8u + lane]);
        uint4 u2 = __ldg(&xw[(unsigned)i0.z * 8u + lane]);
        uint4 u3 = __ldg(&xw[(unsigned)i0.w * 8u + lane]);
        uint4 u4 = __ldg(&xw[(unsigned)i1.x * 8u + lane]);
        uint4 u5 = __ldg(&xw[(unsigned)i1.y * 8u + lane]);
        uint4 u6 = __ldg(&xw[(unsigned)i1.z * 8u + lane]);
        uint4 u7 = __ldg(&xw[(unsigned)i1.w * 8u + lane]);
        acc_pair(acc, u0, u1);
        acc_pair(acc, u2, u3);
        acc_pair(acc, u4, u5);
        acc_pair(acc, u6, u7);
    }
    for (; k + 2 <= e; k += 2) {
        int r0 = __ldg(&g_adj[k]);
        int r1 = __ldg(&g_adj[k + 1]);
        uint4 u0 = __ldg(&xw[(unsigned)r0 * 8u + lane]);
        uint4 u1 = __ldg(&xw[(unsigned)r1 * 8u + lane]);
        acc_pair(acc, u0, u1);
    }
    if (k < e) {
        int r = __ldg(&g_adj[k]);
        uint4 u = __ldg(&xw[(unsigned)r * 8u + lane]);
        acc_one(acc, u);
    }

    float di = __ldg(&g_dinv[node]);
    const float4* b14 = (const float4*)b1;
    float4 bb0 = __ldg(&b14[lane * 2]);
    float4 bb1 = __ldg(&b14[lane * 2 + 1]);
    __half2 o[4];
    o[0] = __floats2half2_rn(fmaxf(fmaf(di, acc[0], bb0.x), 0.f),
                             fmaxf(fmaf(di, acc[1], bb0.y), 0.f));
    o[1] = __floats2half2_rn(fmaxf(fmaf(di, acc[2], bb0.z), 0.f),
                             fmaxf(fmaf(di, acc[3], bb0.w), 0.f));
    o[2] = __floats2half2_rn(fmaxf(fmaf(di, acc[4], bb1.x), 0.f),
                             fmaxf(fmaf(di, acc[5], bb1.y), 0.f));
    o[3] = __floats2half2_rn(fmaxf(fmaf(di, acc[6], bb1.z), 0.f),
                             fmaxf(fmaf(di, acc[7], bb1.w), 0.f));
    *(uint4*)&g_h1[node * 64u + lane * 8u] = *(const uint4*)o;
}

// ---------------- GEMM2: g_h2[N,40](fp16) = dinv[row] * (h1(fp16)[N,64] @ W2[64,40]) --------
__global__ __launch_bounds__(256, 3) void gemm2_kernel(const float* __restrict__ W) {
    __shared__ float Ws[64 * 40];
    int tid = threadIdx.x;
    const float4* W4 = (const float4*)W;
    float4* Ws4 = (float4*)Ws;
#pragma unroll
    for (int i = 0; i < 3; i++) {
        int idx = tid + i * 256;
        if (idx < 640) Ws4[idx] = W4[idx];
    }
    __syncthreads();

    int m0 = blockIdx.x * 128;
    int ty = tid >> 3, tx = tid & 7;
    int r0 = m0 + ty * 4;
    int c0 = tx * 5;
    if (r0 + 4 > NN) return;

    unsigned long long acc2[4][2];
    float acc1[4];
#pragma unroll
    for (int i = 0; i < 4; i++) {
        acc2[i][0] = pk2(0.f, 0.f);
        acc2[i][1] = pk2(0.f, 0.f);
        acc1[i] = 0.f;
    }

    const uint4* H8 = (const uint4*)g_h1;
    for (int k8 = 0; k8 < 8; k8++) {
        float a[4][8];
#pragma unroll
        for (int i = 0; i < 4; i++) {
            uint4 v = __ldg(&H8[(unsigned)(r0 + i) * 8u + k8]);
            const __half2* hp = (const __half2*)&v;
#pragma unroll
            for (int j = 0; j < 4; j++) {
                float2 f = __half22float2(hp[j]);
                a[i][2 * j] = f.x;
                a[i][2 * j + 1] = f.y;
            }
        }
#pragma unroll
        for (int kk = 0; kk < 8; kk++) {
            const float* brow = &Ws[(k8 * 8 + kk) * 40 + c0];
            unsigned long long bp0 = pk2(brow[0], brow[1]);
            unsigned long long bp1 = pk2(brow[2], brow[3]);
            float b4 = brow[4];
#pragma unroll
            for (int i = 0; i < 4; i++) {
                float av = a[i][kk];
                unsigned long long av2 = pk2(av, av);
                fma2(acc2[i][0], av2, bp0);
                fma2(acc2[i][1], av2, bp1);
                acc1[i] = fmaf(av, b4, acc1[i]);
            }
        }
    }

#pragma unroll
    for (int i = 0; i < 4; i++) {
        int row = r0 + i;
        float di = __ldg(&g_dinv[row]);
        float v0, v1, v2, v3;
        upk2(acc2[i][0], v0, v1);
        upk2(acc2[i][1], v2, v3);
        __half* dst = &g_h2[(unsigned)row * 40 + c0];
        dst[0] = __float2half_rn(di * v0);
        dst[1] = __float2half_rn(di * v1);
        dst[2] = __float2half_rn(di * v2);
        dst[3] = __float2half_rn(di * v3);
        dst[4] = __float2half_rn(di * acc1[i]);
    }
}

// ---------------- agg2: out = dinv[c]*(sum_r scaled[r] + scaled[c]) + b2 ----------------
__global__ void agg2_kernel(const float* __restrict__ b2, float* __restrict__ out) {
    unsigned gtid = blockIdx.x * blockDim.x + threadIdx.x;
    unsigned wid = gtid >> 5;
    unsigned lane = gtid & 31;
    unsigned g = lane / 5;
    unsigned sub = lane - g * 5;
    if (g >= 6) return;
    unsigned node = wid * 6 + g;
    if (node >= NN) return;
    const uint4* hh = (const uint4*)g_h2;

    float acc[8];
    {
        uint4 sv = __ldg(&hh[node * 5u + sub]);
        const __half2* hp = (const __half2*)&sv;
#pragma unroll
        for (int j = 0; j < 4; j++) {
            float2 f = __half22float2(hp[j]);
            acc[2 * j] = f.x;
            acc[2 * j + 1] = f.y;
        }
    }

    unsigned s = node * ELLW;
    unsigned e = s + (unsigned)__ldg(&g_cnt[node]);
    unsigned k = s;
    const int4* adj4 = (const int4*)g_adj;
    for (; k + 8 <= e; k += 8) {
        int4 i0 = __ldg(&adj4[k >> 2]);
        int4 i1 = __ldg(&adj4[(k >> 2) + 1]);
        uint4 u0 = __ldg(&hh[(unsigned)i0.x * 5u + sub]);
        uint4 u1 = __ldg(&hh[(unsigned)i0.y * 5u + sub]);
        uint4 u2 = __ldg(&hh[(unsigned)i0.z * 5u + sub]);
        uint4 u3 = __ldg(&hh[(unsigned)i0.w * 5u + sub]);
        uint4 u4 = __ldg(&hh[(unsigned)i1.x * 5u + sub]);
        uint4 u5 = __ldg(&hh[(unsigned)i1.y * 5u + sub]);
        uint4 u6 = __ldg(&hh[(unsigned)i1.z * 5u + sub]);
        uint4 u7 = __ldg(&hh[(unsigned)i1.w * 5u + sub]);
        acc_pair(acc, u0, u1);
        acc_pair(acc, u2, u3);
        acc_pair(acc, u4, u5);
        acc_pair(acc, u6, u7);
    }
    for (; k + 2 <= e; k += 2) {
        int r0 = __ldg(&g_adj[k]);
        int r1 = __ldg(&g_adj[k + 1]);
        uint4 u0 = __ldg(&hh[(unsigned)r0 * 5u + sub]);
        uint4 u1 = __ldg(&hh[(unsigned)r1 * 5u + sub]);
        acc_pair(acc, u0, u1);
    }
    if (k < e) {
        int r = __ldg(&g_adj[k]);
        uint4 u = __ldg(&hh[(unsigned)r * 5u + sub]);
        acc_one(acc, u);
    }

    float di = __ldg(&g_dinv[node]);
    const float4* b24 = (const float4*)b2;
    float4 bb0 = __ldg(&b24[sub * 2]);
    float4 bb1 = __ldg(&b24[sub * 2 + 1]);
    float4 o0, o1;
    o0.x = fmaf(di, acc[0], bb0.x);
    o0.y = fmaf(di, acc[1], bb0.y);
    o0.z = fmaf(di, acc[2], bb0.z);
    o0.w = fmaf(di, acc[3], bb0.w);
    o1.x = fmaf(di, acc[4], bb1.x);
    o1.y = fmaf(di, acc[5], bb1.y);
    o1.z = fmaf(di, acc[6], bb1.z);
    o1.w = fmaf(di, acc[7], bb1.w);
    float4* dst = (float4*)&out[(unsigned)node * 40 + sub * 8];
    dst[0] = o0;
    dst[1] = o1;
}

// ---------------- launch ----------------
extern "C" void kernel_launch(void* const* d_in, const int* in_sizes, int n_in,
                              void* d_out, int out_size) {
    const float* x  = (const float*)d_in[0];
    const void*  ei = d_in[1];
    const float* W1 = (const float*)d_in[2];
    const float* b1 = (const float*)d_in[3];
    const float* W2 = (const float*)d_in[4];
    const float* b2 = (const float*)d_in[5];
    float* out = (float*)d_out;

    init_kernel<<<(NN + 255) / 256, 256>>>(ei);
    fused_g1_scatter_kernel<<<G1_BLOCKS + SC_BLOCKS, 256>>>(x, W1, ei);
    dinv_scale_kernel<<<(NN * 8 + 255) / 256, 256>>>();
    agg1_kernel<<<(NN * 8 + 255) / 256, 256>>>(b1);
    gemm2_kernel<<<(NN + 127) / 128, 256>>>(W2);
    agg2_kernel<<<(NN + 47) / 48, 256>>>(b2, out);
}

// round 13
// speedup vs baseline: 1.4064x; 1.0610x over previous
#include <cuda_runtime.h>
#include <cuda_fp16.h>
#include <cstdint>

#define NN 100000
#define EE 1600000
#define INCH 128
#define HID 64
#define OUTC 40
#define ELLW 64   // max degree capacity; Poisson(16) -> P(deg>=64) ~ e^-40, safe

#define G1_BLOCKS ((NN + 127) / 128)   // 782
#define SC_BLOCKS 768
#define SP 136    // smem stride (halves) for W1^T tiles (conflict-free B-fragment LDS)
#define SP2 72    // smem stride (halves) for W2^T tiles (bank = 4g+t, conflict-free)

// ---------------- scratch (device globals; no allocation allowed) ----------------
__device__ int     g_cnt[NN];
__device__ __align__(16) int g_adj[(size_t)NN * ELLW];  // ELL adjacency (16B-aligned rows)
__device__ float   g_dinv[NN];
__device__ __align__(16) __half g_xw[(size_t)NN * HID];   // dinv[r] * (x @ W1)[r]
__device__ __align__(16) __half g_h1[(size_t)NN * HID];   // relu(agg1), fp16
__device__ __align__(16) __half g_h2[(size_t)NN * OUTC];  // dinv[r] * (h1 @ W2)[r]
__device__ int     g_is64;

// ---------------- HMMA m16n8k16 (row.col, f16 in, f32 acc) ----------------
__device__ __forceinline__ void mma16816(float* d, const unsigned* a, unsigned b0, unsigned b1) {
    asm volatile(
        "mma.sync.aligned.m16n8k16.row.col.f32.f16.f16.f32 "
        "{%0,%1,%2,%3}, {%4,%5,%6,%7}, {%8,%9}, {%0,%1,%2,%3};"
        : "+f"(d[0]), "+f"(d[1]), "+f"(d[2]), "+f"(d[3])
        : "r"(a[0]), "r"(a[1]), "r"(a[2]), "r"(a[3]), "r"(b0), "r"(b1));
}

// split float2 -> hi half2 + lo (residual) half2
__device__ __forceinline__ void split_f2(float2 f, unsigned& hi, unsigned& lo) {
    __half2 h = __floats2half2_rn(f.x, f.y);
    float2 hf = __half22float2(h);
    __half2 l = __floats2half2_rn(f.x - hf.x, f.y - hf.y);
    hi = *(unsigned*)&h;
    lo = *(unsigned*)&l;
}

// ---------------- init: zero counters + dtype sniff (fused) ----------------
__global__ void init_kernel(const void* ei) {
    int i = blockIdx.x * blockDim.x + threadIdx.x;
    if (i < NN) g_cnt[i] = 0;
    if (i == 0) {
        const unsigned int* w = (const unsigned int*)ei;
        int is64 = 1;
        for (int j = 0; j < 64; j++) {
            if (w[2 * j + 1] != 0u) { is64 = 0; break; }
        }
        g_is64 = is64;
    }
}

// ---------------- fused: tensor-core GEMM1 (blocks [0,782)) + ELL scatter ----------------
// GEMM1: g_xw[N,64](fp16, UNSCALED) = x[N,128] @ W1[128,64]
__global__ __launch_bounds__(256) void fused_g1_scatter_kernel(
    const float* __restrict__ A, const float* __restrict__ W, const void* __restrict__ ei) {
    __shared__ __half Wh[64 * SP];
    __shared__ __half Wl[64 * SP];

    int bx = blockIdx.x;
    if (bx >= G1_BLOCKS) {
        // ---- scatter path ----
        int tid = (bx - G1_BLOCKS) * 256 + threadIdx.x;
        int stride = SC_BLOCKS * 256;
        int is64 = g_is64;
        if (is64) {
            const longlong2* r2 = (const longlong2*)ei;
            const longlong2* c2 = (const longlong2*)((const long long*)ei + EE);
            for (int e = tid; e < EE / 2; e += stride) {
                longlong2 rr = __ldg(&r2[e]);
                longlong2 cc = __ldg(&c2[e]);
                int c0 = (int)cc.x, c1 = (int)cc.y;
                int p0 = atomicAdd(&g_cnt[c0], 1);
                int p1 = atomicAdd(&g_cnt[c1], 1);
                g_adj[(unsigned)c0 * ELLW + p0] = (int)rr.x;
                g_adj[(unsigned)c1 * ELLW + p1] = (int)rr.y;
            }
        } else {
            const int2* r2 = (const int2*)ei;
            const int2* c2 = (const int2*)((const int*)ei + EE);
            for (int e = tid; e < EE / 2; e += stride) {
                int2 rr = __ldg(&r2[e]);
                int2 cc = __ldg(&c2[e]);
                int p0 = atomicAdd(&g_cnt[cc.x], 1);
                int p1 = atomicAdd(&g_cnt[cc.y], 1);
                g_adj[(unsigned)cc.x * ELLW + p0] = rr.x;
                g_adj[(unsigned)cc.y * ELLW + p1] = rr.y;
            }
        }
        return;
    }

    // ---- GEMM path ----
    int tid = threadIdx.x;
    for (int idx = tid; idx < 128 * 64; idx += 256) {
        int k = idx >> 6, n = idx & 63;
        float w = __ldg(&W[idx]);
        __half h = __float2half_rn(w);
        Wh[n * SP + k] = h;
        Wl[n * SP + k] = __float2half_rn(w - __half2float(h));
    }
    __syncthreads();

    int warp = tid >> 5, lane = tid & 31;
    int g = lane >> 2, t = lane & 3;
    int row0 = bx * 128 + warp * 16 + g;    // rows row0 and row0+8
    int ra = (row0 < NN) ? row0 : (NN - 1);
    int rb = (row0 + 8 < NN) ? (row0 + 8) : (NN - 1);
    const float* Ar0 = A + (size_t)ra * 128;
    const float* Ar1 = A + (size_t)rb * 128;

    float d[8][4];
#pragma unroll
    for (int j = 0; j < 8; j++)
#pragma unroll
        for (int q = 0; q < 4; q++) d[j][q] = 0.f;

#pragma unroll
    for (int kk = 0; kk < 8; kk++) {
        int kb = kk * 16 + t * 2;
        float2 L0 = __ldg((const float2*)(Ar0 + kb));
        float2 L1 = __ldg((const float2*)(Ar1 + kb));
        float2 L2 = __ldg((const float2*)(Ar0 + kb + 8));
        float2 L3 = __ldg((const float2*)(Ar1 + kb + 8));
        unsigned ah[4], al[4];
        split_f2(L0, ah[0], al[0]);
        split_f2(L1, ah[1], al[1]);
        split_f2(L2, ah[2], al[2]);
        split_f2(L3, ah[3], al[3]);
#pragma unroll
        for (int j = 0; j < 8; j++) {
            int n = j * 8 + g;
            const __half* ph = &Wh[n * SP + kk * 16 + t * 2];
            const __half* pl = &Wl[n * SP + kk * 16 + t * 2];
            unsigned bh0 = *(const unsigned*)ph;
            unsigned bh1 = *(const unsigned*)(ph + 8);
            unsigned bl0 = *(const unsigned*)pl;
            unsigned bl1 = *(const unsigned*)(pl + 8);
            mma16816(d[j], ah, bh0, bh1);
            mma16816(d[j], ah, bl0, bl1);
            mma16816(d[j], al, bh0, bh1);
        }
    }

#pragma unroll
    for (int j = 0; j < 8; j++) {
        int c0 = j * 8 + t * 2;
        if (row0 < NN) {
            __half2 p = __floats2half2_rn(d[j][0], d[j][1]);
            *(unsigned*)&g_xw[(unsigned)row0 * 64 + c0] = *(unsigned*)&p;
        }
        if (row0 + 8 < NN) {
            __half2 p = __floats2half2_rn(d[j][2], d[j][3]);
            *(unsigned*)&g_xw[(unsigned)(row0 + 8) * 64 + c0] = *(unsigned*)&p;
        }
    }
}

// ---------------- dinv + scale xw: di = rsqrt(cnt+1); g_xw *= di ----------------
__global__ void dinv_scale_kernel() {
    unsigned gid = blockIdx.x * blockDim.x + threadIdx.x;
    unsigned node = gid >> 3;
    unsigned lane = gid & 7;
    if (node >= NN) return;
    float di = rsqrtf((float)(__ldg(&g_cnt[node]) + 1));  // +1 self-loop
    if (lane == 0) g_dinv[node] = di;
    uint4* p = (uint4*)&g_xw[node * 64u + lane * 8u];
    uint4 v = *p;
    __half2* hp = (__half2*)&v;
#pragma unroll
    for (int j = 0; j < 4; j++) {
        float2 f = __half22float2(hp[j]);
        hp[j] = __floats2half2_rn(di * f.x, di * f.y);
    }
    *p = v;
}

// ---------------- agg helpers ----------------
__device__ __forceinline__ void acc_pair(float* acc, const uint4& ua, const uint4& ub) {
    const __half2* pa = (const __half2*)&ua;
    const __half2* pb = (const __half2*)&ub;
#pragma unroll
    for (int j = 0; j < 4; j++) {
        float2 f = __half22float2(__hadd2(pa[j], pb[j]));
        acc[2 * j] += f.x;
        acc[2 * j + 1] += f.y;
    }
}
__device__ __forceinline__ void acc_one(float* acc, const uint4& u) {
    const __half2* p = (const __half2*)&u;
#pragma unroll
    for (int j = 0; j < 4; j++) {
        float2 f = __half22float2(p[j]);
        acc[2 * j] += f.x;
        acc[2 * j + 1] += f.y;
    }
}

// ---------------- agg1: h1 = relu(dinv[c]*(sum_r scaled[r] + scaled[c]) + b1) ----------------
__global__ void agg1_kernel(const float* __restrict__ b1) {
    unsigned gid = blockIdx.x * blockDim.x + threadIdx.x;
    unsigned node = gid >> 3;
    unsigned lane = gid & 7;
    if (node >= NN) return;
    const uint4* xw = (const uint4*)g_xw;

    float acc[8];
    {
        uint4 sv = __ldg(&xw[node * 8u + lane]);
        const __half2* hp = (const __half2*)&sv;
#pragma unroll
        for (int j = 0; j < 4; j++) {
            float2 f = __half22float2(hp[j]);
            acc[2 * j] = f.x;
            acc[2 * j + 1] = f.y;
        }
    }

    unsigned s = node * ELLW;
    unsigned e = s + (unsigned)__ldg(&g_cnt[node]);
    unsigned k = s;
    const int4* adj4 = (const int4*)g_adj;
    for (; k + 8 <= e; k += 8) {
        int4 i0 = __ldg(&adj4[k >> 2]);
        int4 i1 = __ldg(&adj4[(k >> 2) + 1]);
        uint4 u0 = __ldg(&xw[(unsigned)i0.x * 8u + lane]);
        uint4 u1 = __ldg(&xw[(unsigned)i0.y * 8u + lane]);
        uint4 u2 = __ldg(&xw[(unsigned)i0.z * 8u + lane]);
        uint4 u3 = __ldg(&xw[(unsigned)i0.w * 8u + lane]);
        uint4 u4 = __ldg(&xw[(unsigned)i1.x * 8u + lane]);
        uint4 u5 = __ldg(&xw[(unsigned)i1.y * 8u + lane]);
        uint4 u6 = __ldg(&xw[(unsigned)i1.z * 8u + lane]);
        uint4 u7 = __ldg(&xw[(unsigned)i1.w * 8u + lane]);
        acc_pair(acc, u0, u1);
        acc_pair(acc, u2, u3);
        acc_pair(acc, u4, u5);
        acc_pair(acc, u6, u7);
    }
    for (; k + 2 <= e; k += 2) {
        int r0 = __ldg(&g_adj[k]);
        int r1 = __ldg(&g_adj[k + 1]);
        uint4 u0 = __ldg(&xw[(unsigned)r0 * 8u + lane]);
        uint4 u1 = __ldg(&xw[(unsigned)r1 * 8u + lane]);
        acc_pair(acc, u0, u1);
    }
    if (k < e) {
        int r = __ldg(&g_adj[k]);
        uint4 u = __ldg(&xw[(unsigned)r * 8u + lane]);
        acc_one(acc, u);
    }

    float di = __ldg(&g_dinv[node]);
    const float4* b14 = (const float4*)b1;
    float4 bb0 = __ldg(&b14[lane * 2]);
    float4 bb1 = __ldg(&b14[lane * 2 + 1]);
    __half2 o[4];
    o[0] = __floats2half2_rn(fmaxf(fmaf(di, acc[0], bb0.x), 0.f),
                             fmaxf(fmaf(di, acc[1], bb0.y), 0.f));
    o[1] = __floats2half2_rn(fmaxf(fmaf(di, acc[2], bb0.z), 0.f),
                             fmaxf(fmaf(di, acc[3], bb0.w), 0.f));
    o[2] = __floats2half2_rn(fmaxf(fmaf(di, acc[4], bb1.x), 0.f),
                             fmaxf(fmaf(di, acc[5], bb1.y), 0.f));
    o[3] = __floats2half2_rn(fmaxf(fmaf(di, acc[6], bb1.z), 0.f),
                             fmaxf(fmaf(di, acc[7], bb1.w), 0.f));
    *(uint4*)&g_h1[node * 64u + lane * 8u] = *(const uint4*)o;
}

// ---------------- GEMM2 (HMMA): g_h2[N,40](fp16) = dinv[row] * (h1(fp16)[N,64] @ W2[64,40]) --
// 8 warps x (16 rows x 40 cols). A fp16 from gmem (exact, no split); W2 hi/lo split in smem.
__global__ __launch_bounds__(256) void gemm2_kernel(const float* __restrict__ W) {
    __shared__ __half Wh[40 * SP2];
    __shared__ __half Wl[40 * SP2];
    int tid = threadIdx.x;
    // W2^T hi/lo: Wh[n*SP2 + k] = hi(W[k][n]), k<64, n<40
    for (int idx = tid; idx < 64 * 40; idx += 256) {
        int k = idx / 40, n = idx - k * 40;
        float w = __ldg(&W[idx]);
        __half h = __float2half_rn(w);
        Wh[n * SP2 + k] = h;
        Wl[n * SP2 + k] = __float2half_rn(w - __half2float(h));
    }
    __syncthreads();

    int warp = tid >> 5, lane = tid & 31;
    int g = lane >> 2, t = lane & 3;
    int row0 = blockIdx.x * 128 + warp * 16 + g;   // rows row0, row0+8
    int ra = (row0 < NN) ? row0 : (NN - 1);
    int rb = (row0 + 8 < NN) ? (row0 + 8) : (NN - 1);
    const __half* H0 = g_h1 + (unsigned)ra * 64;
    const __half* H1 = g_h1 + (unsigned)rb * 64;

    float d[5][4];
#pragma unroll
    for (int j = 0; j < 5; j++)
#pragma unroll
        for (int q = 0; q < 4; q++) d[j][q] = 0.f;

#pragma unroll
    for (int kk = 0; kk < 4; kk++) {
        int kb = kk * 16 + t * 2;
        unsigned a[4];
        a[0] = *(const unsigned*)(H0 + kb);        // (g,   k..k+1)
        a[1] = *(const unsigned*)(H1 + kb);        // (g+8, k..k+1)
        a[2] = *(const unsigned*)(H0 + kb + 8);    // (g,   k+8..k+9)
        a[3] = *(const unsigned*)(H1 + kb + 8);    // (g+8, k+8..k+9)
#pragma unroll
        for (int j = 0; j < 5; j++) {
            int n = j * 8 + g;
            const __half* ph = &Wh[n * SP2 + kk * 16 + t * 2];
            const __half* pl = &Wl[n * SP2 + kk * 16 + t * 2];
            unsigned bh0 = *(const unsigned*)ph;
            unsigned bh1 = *(const unsigned*)(ph + 8);
            unsigned bl0 = *(const unsigned*)pl;
            unsigned bl1 = *(const unsigned*)(pl + 8);
            mma16816(d[j], a, bh0, bh1);
            mma16816(d[j], a, bl0, bl1);
        }
    }

    // Epilogue: d[j] = {(row0,c0),(row0,c0+1),(row0+8,c0),(row0+8,c0+1)}, c0 = j*8 + t*2.
    float di0 = (row0 < NN) ? __ldg(&g_dinv[row0]) : 0.f;
    float di1 = (row0 + 8 < NN) ? __ldg(&g_dinv[row0 + 8]) : 0.f;
#pragma unroll
    for (int j = 0; j < 5; j++) {
        int c0 = j * 8 + t * 2;
        if (row0 < NN) {
            __half2 p = __floats2half2_rn(di0 * d[j][0], di0 * d[j][1]);
            *(unsigned*)&g_h2[(unsigned)row0 * 40 + c0] = *(unsigned*)&p;   // 4B aligned
        }
        if (row0 + 8 < NN) {
            __half2 p = __floats2half2_rn(di1 * d[j][2], di1 * d[j][3]);
            *(unsigned*)&g_h2[(unsigned)(row0 + 8) * 40 + c0] = *(unsigned*)&p;
        }
    }
}

// ---------------- agg2: out = dinv[c]*(sum_r scaled[r] + scaled[c]) + b2 ----------------
__global__ void agg2_kernel(const float* __restrict__ b2, float* __restrict__ out) {
    unsigned gtid = blockIdx.x * blockDim.x + threadIdx.x;
    unsigned wid = gtid >> 5;
    unsigned lane = gtid & 31;
    unsigned g = lane / 5;
    unsigned sub = lane - g * 5;
    if (g >= 6) return;
    unsigned node = wid * 6 + g;
    if (node >= NN) return;
    const uint4* hh = (const uint4*)g_h2;

    float acc[8];
    {
        uint4 sv = __ldg(&hh[node * 5u + sub]);
        const __half2* hp = (const __half2*)&sv;
#pragma unroll
        for (int j = 0; j < 4; j++) {
            float2 f = __half22float2(hp[j]);
            acc[2 * j] = f.x;
            acc[2 * j + 1] = f.y;
        }
    }

    unsigned s = node * ELLW;
    unsigned e = s + (unsigned)__ldg(&g_cnt[node]);
    unsigned k = s;
    const int4* adj4 = (const int4*)g_adj;
    for (; k + 8 <= e; k += 8) {
        int4 i0 = __ldg(&adj4[k >> 2]);
        int4 i1 = __ldg(&adj4[(k >> 2) + 1]);
        uint4 u0 = __ldg(&hh[(unsigned)i0.x * 5u + sub]);
        uint4 u1 = __ldg(&hh[(unsigned)i0.y * 5u + sub]);
        uint4 u2 = __ldg(&hh[(unsigned)i0.z * 5u + sub]);
        uint4 u3 = __ldg(&hh[(unsigned)i0.w * 5u + sub]);
        uint4 u4 = __ldg(&hh[(unsigned)i1.x * 5u + sub]);
        uint4 u5 = __ldg(&hh[(unsigned)i1.y * 5u + sub]);
        uint4 u6 = __ldg(&hh[(unsigned)i1.z * 5u + sub]);
        uint4 u7 = __ldg(&hh[(unsigned)i1.w * 5u + sub]);
        acc_pair(acc, u0, u1);
        acc_pair(acc, u2, u3);
        acc_pair(acc, u4, u5);
        acc_pair(acc, u6, u7);
    }
    for (; k + 2 <= e; k += 2) {
        int r0 = __ldg(&g_adj[k]);
        int r1 = __ldg(&g_adj[k + 1]);
        uint4 u0 = __ldg(&hh[(unsigned)r0 * 5u + sub]);
        uint4 u1 = __ldg(&hh[(unsigned)r1 * 5u + sub]);
        acc_pair(acc, u0, u1);
    }
    if (k < e) {
        int r = __ldg(&g_adj[k]);
        uint4 u = __ldg(&hh[(unsigned)r * 5u + sub]);
        acc_one(acc, u);
    }

    float di = __ldg(&g_dinv[node]);
    const float4* b24 = (const float4*)b2;
    float4 bb0 = __ldg(&b24[sub * 2]);
    float4 bb1 = __ldg(&b24[sub * 2 + 1]);
    float4 o0, o1;
    o0.x = fmaf(di, acc[0], bb0.x);
    o0.y = fmaf(di, acc[1], bb0.y);
    o0.z = fmaf(di, acc[2], bb0.z);
    o0.w = fmaf(di, acc[3], bb0.w);
    o1.x = fmaf(di, acc[4], bb1.x);
    o1.y = fmaf(di, acc[5], bb1.y);
    o1.z = fmaf(di, acc[6], bb1.z);
    o1.w = fmaf(di, acc[7], bb1.w);
    float4* dst = (float4*)&out[(unsigned)node * 40 + sub * 8];
    dst[0] = o0;
    dst[1] = o1;
}

// ---------------- launch ----------------
extern "C" void kernel_launch(void* const* d_in, const int* in_sizes, int n_in,
                              void* d_out, int out_size) {
    const float* x  = (const float*)d_in[0];
    const void*  ei = d_in[1];
    const float* W1 = (const float*)d_in[2];
    const float* b1 = (const float*)d_in[3];
    const float* W2 = (const float*)d_in[4];
    const float* b2 = (const float*)d_in[5];
    float* out = (float*)d_out;

    init_kernel<<<(NN + 255) / 256, 256>>>(ei);
    fused_g1_scatter_kernel<<<G1_BLOCKS + SC_BLOCKS, 256>>>(x, W1, ei);
    dinv_scale_kernel<<<(NN * 8 + 255) / 256, 256>>>();
    agg1_kernel<<<(NN * 8 + 255) / 256, 256>>>(b1);
    gemm2_kernel<<<(NN + 127) / 128, 256>>>(W2);
    agg2_kernel<<<(NN + 47) / 48, 256>>>(b2, out);
}